// round 5
// baseline (speedup 1.0000x reference)
#include <cuda_runtime.h>
#include <cuda_bf16.h>
#include <cstdint>

#define BB 256
#define NN 128
#define CC 256

// B = W^T hi/lo images: [8 kchunks][256 rows][32 bf16] -> 128KB each
__device__ __align__(16) unsigned char g_Bhi[131072];
__device__ __align__(16) unsigned char g_Blo[131072];

__device__ __forceinline__ uint32_t smem_u32(const void* p) {
    uint32_t a;
    asm("{ .reg .u64 t; cvta.to.shared.u64 t, %1; cvt.u32.u64 %0, t; }"
        : "=r"(a) : "l"(p));
    return a;
}

__device__ __forceinline__ void ldsm_x4(uint32_t& r0, uint32_t& r1, uint32_t& r2,
                                        uint32_t& r3, uint32_t addr) {
    asm volatile("ldmatrix.sync.aligned.m8n8.x4.shared.b16 {%0,%1,%2,%3}, [%4];"
                 : "=r"(r0), "=r"(r1), "=r"(r2), "=r"(r3) : "r"(addr));
}

__device__ __forceinline__ void mma16816(float* d, const uint32_t* a, const uint32_t* b) {
    asm volatile(
        "mma.sync.aligned.m16n8k16.row.col.f32.bf16.bf16.f32 "
        "{%0,%1,%2,%3}, {%4,%5,%6,%7}, {%8,%9}, {%0,%1,%2,%3};"
        : "+f"(d[0]), "+f"(d[1]), "+f"(d[2]), "+f"(d[3])
        : "r"(a[0]), "r"(a[1]), "r"(a[2]), "r"(a[3]), "r"(b[0]), "r"(b[1]));
}

__device__ __forceinline__ void cp16(uint32_t dst, const void* src) {
    asm volatile("cp.async.cg.shared.global [%0], [%1], 16;" :: "r"(dst), "l"(src));
}

__device__ __forceinline__ void split_pack(const float* a, uint32_t* hi, uint32_t* lo) {
    #pragma unroll
    for (int u = 0; u < 4; u++) {
        float a0 = a[2 * u], a1 = a[2 * u + 1];
        __nv_bfloat16 h0 = __float2bfloat16(a0);
        __nv_bfloat16 h1 = __float2bfloat16(a1);
        __nv_bfloat16 l0 = __float2bfloat16(a0 - __bfloat162float(h0));
        __nv_bfloat16 l1 = __float2bfloat16(a1 - __bfloat162float(h1));
        hi[u] = ((uint32_t)__bfloat16_as_ushort(h1) << 16) | __bfloat16_as_ushort(h0);
        lo[u] = ((uint32_t)__bfloat16_as_ushort(l1) << 16) | __bfloat16_as_ushort(l0);
    }
}

// ---------------------------------------------------------------------------
// Kernel 0: W^T hi/lo images (coalesced).
// ---------------------------------------------------------------------------
__global__ void __launch_bounds__(256) prep_w_kernel(const float* __restrict__ W) {
    int e = blockIdx.x * 256 + threadIdx.x;   // 8192
    int lane = e & 31;
    int w = e >> 5;
    int n = (w & 7) * 32 + lane;
    int k0 = (w >> 3) * 8;
    float a[8];
    #pragma unroll
    for (int u = 0; u < 8; u++) a[u] = W[(size_t)(k0 + u) * CC + n];
    uint32_t hi[4], lo[4];
    split_pack(a, hi, lo);
    size_t off = (size_t)(k0 >> 5) * 16384 + n * 64 + (k0 & 31) * 2;
    *(uint4*)(g_Bhi + off) = make_uint4(hi[0], hi[1], hi[2], hi[3]);
    *(uint4*)(g_Blo + off) = make_uint4(lo[0], lo[1], lo[2], lo[3]);
}

// ---------------------------------------------------------------------------
// Fused kernel. SMEM plan:
//  [SA, 128KB): phase 1 = staged x (row j at j*1024, linear);
//               phase 2 = A bf16 hi/lo image [8 chunks 16KB][128 rows 128B],
//               quad-XOR swizzle for conflict-free ldmatrix.
//  [SB, 80KB):  B double-buffer stages (rows padded 80B). Stage 1 aliased by nb
//               during conv (nb dead before first write to stage 1).
// ---------------------------------------------------------------------------
#define ROWPAD 80
#define SA      0               // 131072
#define SB      131072          // 2 stages x 40960
#define ST_BLO  20480
#define STAGE   40960
#define SNB     172032          // nb ushort[128][128] = 32768 (aliases B stage 1)
#define SPAR    212992          // db, gamma, beta (3 x 1024)
#define SRED    216064          // redS 4096 + redQ 4096 (aliased by shK during conv)
#define SMI     224256          // float2[128]
#define SMISC   225280          // shB 1024 | sge 512 | sgp 512 | scnt 512 | wmin 64 | mins 8
#define SMEMT   228352

__global__ void __launch_bounds__(512, 1) fused_kernel(
    const float* __restrict__ x, const float* __restrict__ eta,
    const float* __restrict__ phi, const float* __restrict__ ck,
    const float* __restrict__ cb, const float* __restrict__ db,
    const float* __restrict__ gamma, const float* __restrict__ beta,
    float* __restrict__ out)
{
    extern __shared__ char smem[];
    uint32_t sb = smem_u32(smem);
    int b = blockIdx.x;
    int t = threadIdx.x;
    int lane = t & 31;
    int w = t >> 5;

    const float* xb = x + (size_t)b * NN * CC;

    auto copy_stage = [&](int s, int kc) {
        uint32_t st = sb + SB + s * STAGE;
        #pragma unroll
        for (int p = 0; p < 2; p++) {
            int idx = t + p * 512;
            int row = idx >> 2, seg = idx & 3;
            uint32_t d = st + row * ROWPAD + seg * 16;
            cp16(d, g_Bhi + (size_t)kc * 16384 + idx * 16);
            cp16(d + ST_BLO, g_Blo + (size_t)kc * 16384 + idx * 16);
        }
    };

    // ---- prefetch: B chunk 0 + whole x batch into SA (hidden under bins/nb) ----
    copy_stage(0, 0);
    #pragma unroll
    for (int p = 0; p < 16; p++) {
        int idx = t + p * 512;                 // 8192 uint4 = 128KB
        cp16(sb + SA + idx * 16, (const char*)xb + idx * 16);
    }
    asm volatile("cp.async.commit_group;" ::: "memory");

    // params
    if (t < 256) {
        ((float*)(smem + SPAR))[t]        = db[t];
        ((float*)(smem + SPAR + 1024))[t] = gamma[t];
        ((float*)(smem + SPAR + 2048))[t] = beta[t];
    }

    // ---- conv-phase shared views ----
    float* shB   = (float*)(smem + SMISC);
    int*   sge   = (int*)(smem + SMISC + 1024);
    int*   sgp   = (int*)(smem + SMISC + 1536);
    int*   scnt  = (int*)(smem + SMISC + 2048);
    float* wmin  = (float*)(smem + SMISC + 2560);
    float* mins  = (float*)(smem + SMISC + 2624);
    float* shK   = (float*)(smem + SRED);
    unsigned short (*nb)[NN] = (unsigned short (*)[NN])(smem + SNB);

    // ---- per-batch min ----
    float ve = (t < NN) ? eta[b * NN + t] : 1e30f;
    float vp = (t < NN) ? phi[b * NN + t] : 1e30f;
    #pragma unroll
    for (int o = 16; o > 0; o >>= 1) {
        ve = fminf(ve, __shfl_xor_sync(0xffffffffu, ve, o));
        vp = fminf(vp, __shfl_xor_sync(0xffffffffu, vp, o));
    }
    if (lane == 0 && w < 4) { wmin[w] = ve; wmin[4 + w] = vp; }
    __syncthreads();
    if (t == 0) {
        mins[0] = fminf(fminf(wmin[0], wmin[1]), fminf(wmin[2], wmin[3]));
        mins[1] = fminf(fminf(wmin[4], wmin[5]), fminf(wmin[6], wmin[7]));
    }
    __syncthreads();
    if (t < NN) {
        sge[t] = (int)((eta[b * NN + t] - mins[0]) / 0.05f);
        sgp[t] = (int)((phi[b * NN + t] - mins[1]) / 0.05f);
    }
    __syncthreads();

    // ---- neighbor lists (t<128), conv weights staged by the rest ----
    if (t < NN) {
        int gi = sge[t], pi = sgp[t];
        int cnt = 0;
        for (int j = 0; j < NN; j++) {
            unsigned dg = (unsigned)(sge[j] - gi + 1);
            unsigned dp = (unsigned)(sgp[j] - pi + 1);
            if (dg <= 2u && dp <= 2u)
                nb[t][cnt++] = (unsigned short)(j | ((dg * 3 + dp) << 8));
        }
        scnt[t] = cnt;
    } else {
        for (int i = t - 128; i < 9 * CC; i += 384) shK[i] = ck[i];
        if (t >= 256) shB[t - 256] = cb[t - 256];
    }
    asm volatile("cp.async.wait_group 0;" ::: "memory");
    __syncthreads();

    // ---- conv from SMEM x; accumulators persist in registers ----
    int c0 = lane * 8;
    float accv[8][8];
    {
        const char* xs = smem + SA;
        #pragma unroll
        for (int s = 0; s < 8; s++) {
            int i = w * 8 + s;
            #pragma unroll
            for (int u = 0; u < 8; u++) accv[s][u] = shB[c0 + u];

            int cnt = scnt[i];
            for (int e = 0; e < cnt; e++) {
                int pk = nb[i][e];
                int j = pk & 0xFF;
                int kk = pk >> 8;
                const float4* xp = (const float4*)(xs + j * 1024 + c0 * 4);
                float4 a0 = xp[0];
                float4 a1 = xp[1];
                const float4* kp = (const float4*)(shK + kk * CC + c0);
                float4 k0 = kp[0];
                float4 k1 = kp[1];
                accv[s][0] += k0.x * a0.x; accv[s][1] += k0.y * a0.y;
                accv[s][2] += k0.z * a0.z; accv[s][3] += k0.w * a0.w;
                accv[s][4] += k1.x * a1.x; accv[s][5] += k1.y * a1.y;
                accv[s][6] += k1.z * a1.z; accv[s][7] += k1.w * a1.w;
            }
        }
    }
    __syncthreads();   // all x reads complete -> safe to overwrite SA with A

    // ---- write A image (bf16 hi/lo, quad-XOR swizzle) ----
    {
        char* achunk = smem + SA + (lane >> 2) * 16384;
        uint32_t qbh = (uint32_t)(lane & 3);
        uint32_t qbl = (uint32_t)(4 + (lane & 3));
        #pragma unroll
        for (int s = 0; s < 8; s++) {
            int i = w * 8 + s;
            uint32_t hi[4], lo[4];
            split_pack(accv[s], hi, lo);
            char* ap = achunk + i * 128;
            uint32_t r7 = (uint32_t)(i & 7);
            *(uint4*)(ap + ((qbh ^ r7) * 16)) = make_uint4(hi[0], hi[1], hi[2], hi[3]);
            *(uint4*)(ap + ((qbl ^ r7) * 16)) = make_uint4(lo[0], lo[1], lo[2], lo[3]);
        }
    }
    __syncthreads();

    // ---- GEMM: M=128 N=256 K=256, 16 warps, warp tile 64x32 ----
    int mw = w & 1;
    int nw = w >> 1;

    float acc[4][4][4];
    #pragma unroll
    for (int i = 0; i < 4; i++)
        #pragma unroll
        for (int j = 0; j < 4; j++)
            #pragma unroll
            for (int d = 0; d < 4; d++) acc[i][j][d] = 0.f;

    int aRow = (lane & 7) + ((lane >> 3) & 1) * 8;
    uint32_t l7 = (uint32_t)(lane & 7);
    uint32_t qk = (uint32_t)(lane >> 4);
    uint32_t qhi[2], qlo[2];
    #pragma unroll
    for (int ks = 0; ks < 2; ks++) {
        qhi[ks] = (((uint32_t)(ks * 2) + qk) ^ l7) * 16;
        qlo[ks] = (((uint32_t)(4 + ks * 2) + qk) ^ l7) * 16;
    }
    uint32_t aBase = sb + SA + (mw * 64 + aRow) * 128;

    int bRow = (lane & 7) + ((lane >= 16) ? 8 : 0);
    uint32_t bKb = (uint32_t)(((lane >> 3) & 1) * 16);

    for (int kc = 0; kc < 8; kc++) {
        asm volatile("cp.async.wait_group 0;" ::: "memory");
        __syncthreads();
        if (kc < 7) {
            copy_stage((kc + 1) & 1, kc + 1);
            asm volatile("cp.async.commit_group;" ::: "memory");
        }

        uint32_t ca = aBase + kc * 16384;
        uint32_t st = sb + SB + (kc & 1) * STAGE;
        uint32_t sBhi = st + (nw * 32 + bRow) * ROWPAD + bKb;
        uint32_t sBlo = sBhi + ST_BLO;

        #pragma unroll
        for (int ks = 0; ks < 2; ks++) {
            uint32_t ahi[4][4], alo[4][4], bhi[4][2], blo[4][2];
            #pragma unroll
            for (int mt = 0; mt < 4; mt++) {
                uint32_t a = ca + mt * 2048;
                ldsm_x4(ahi[mt][0], ahi[mt][1], ahi[mt][2], ahi[mt][3], a + qhi[ks]);
                ldsm_x4(alo[mt][0], alo[mt][1], alo[mt][2], alo[mt][3], a + qlo[ks]);
            }
            #pragma unroll
            for (int np = 0; np < 2; np++) {
                uint32_t r0, r1, r2, r3;
                ldsm_x4(r0, r1, r2, r3, sBhi + np * (16 * ROWPAD) + ks * 32);
                bhi[2 * np][0] = r0; bhi[2 * np][1] = r1;
                bhi[2 * np + 1][0] = r2; bhi[2 * np + 1][1] = r3;
                ldsm_x4(r0, r1, r2, r3, sBlo + np * (16 * ROWPAD) + ks * 32);
                blo[2 * np][0] = r0; blo[2 * np][1] = r1;
                blo[2 * np + 1][0] = r2; blo[2 * np + 1][1] = r3;
            }
            #pragma unroll
            for (int mt = 0; mt < 4; mt++)
                #pragma unroll
                for (int nt = 0; nt < 4; nt++) {
                    mma16816(acc[mt][nt], ahi[mt], bhi[nt]);
                    mma16816(acc[mt][nt], alo[mt], bhi[nt]);
                    mma16816(acc[mt][nt], ahi[mt], blo[nt]);
                }
        }
    }

    // ---- epilogue: bias + LN + residual ----
    const float* s_db = (const float*)(smem + SPAR);
    const float* s_g  = (const float*)(smem + SPAR + 1024);
    const float* s_bt = (const float*)(smem + SPAR + 2048);
    float* redS = (float*)(smem + SRED);
    float* redQ = (float*)(smem + SRED + 4096);
    float2* smi = (float2*)(smem + SMI);

    int qr = lane >> 2, qc = lane & 3;
    int MW = mw * 64, NW = nw * 32;

    float S[4][2], Q[4][2];
    #pragma unroll
    for (int mt = 0; mt < 4; mt++) {
        S[mt][0] = S[mt][1] = 0.f;
        Q[mt][0] = Q[mt][1] = 0.f;
    }
    #pragma unroll
    for (int mt = 0; mt < 4; mt++)
        #pragma unroll
        for (int nt = 0; nt < 4; nt++)
            #pragma unroll
            for (int d = 0; d < 4; d++) {
                int col = NW + nt * 8 + qc * 2 + (d & 1);
                float v = acc[mt][nt][d] + s_db[col];
                acc[mt][nt][d] = v;
                S[mt][d >> 1] += v;
                Q[mt][d >> 1] += v * v;
            }
    #pragma unroll
    for (int mt = 0; mt < 4; mt++)
        #pragma unroll
        for (int h = 0; h < 2; h++) {
            #pragma unroll
            for (int off = 1; off <= 2; off <<= 1) {
                S[mt][h] += __shfl_xor_sync(0xffffffffu, S[mt][h], off);
                Q[mt][h] += __shfl_xor_sync(0xffffffffu, Q[mt][h], off);
            }
        }
    __syncthreads();
    if (qc == 0) {
        #pragma unroll
        for (int mt = 0; mt < 4; mt++)
            #pragma unroll
            for (int h = 0; h < 2; h++) {
                int row = MW + mt * 16 + qr + h * 8;
                redS[row * 8 + nw] = S[mt][h];
                redQ[row * 8 + nw] = Q[mt][h];
            }
    }
    __syncthreads();

    if (t < 128) {
        float s = 0.f, q = 0.f;
        #pragma unroll
        for (int k = 0; k < 8; k++) {
            s += redS[t * 8 + k];
            q += redQ[t * 8 + k];
        }
        float mean = s * (1.0f / 256.0f);
        float var = fmaf(-mean, mean, q * (1.0f / 256.0f));
        smi[t] = make_float2(mean, rsqrtf(var + 1e-6f));
    }
    __syncthreads();

    #pragma unroll
    for (int mt = 0; mt < 4; mt++)
        #pragma unroll
        for (int h = 0; h < 2; h++) {
            int row = MW + mt * 16 + qr + h * 8;
            float2 mv = smi[row];
            size_t rb = ((size_t)b * NN + row) * CC;
            #pragma unroll
            for (int nt = 0; nt < 4; nt++) {
                int col = NW + nt * 8 + qc * 2;
                float2 xv = *(const float2*)(x + rb + col);
                float v0 = (acc[mt][nt][h * 2]     - mv.x) * mv.y * s_g[col]     + s_bt[col]     + xv.x;
                float v1 = (acc[mt][nt][h * 2 + 1] - mv.x) * mv.y * s_g[col + 1] + s_bt[col + 1] + xv.y;
                *(float2*)(out + rb + col) = make_float2(v0, v1);
            }
        }
}

extern "C" void kernel_launch(void* const* d_in, const int* in_sizes, int n_in,
                              void* d_out, int out_size) {
    const float* x   = (const float*)d_in[0];
    const float* eta = (const float*)d_in[1];
    const float* phi = (const float*)d_in[2];
    const float* ck  = (const float*)d_in[3];
    const float* cb  = (const float*)d_in[4];
    const float* dw  = (const float*)d_in[5];
    const float* db  = (const float*)d_in[6];
    const float* gm  = (const float*)d_in[7];
    const float* bt  = (const float*)d_in[8];
    float* out = (float*)d_out;

    cudaFuncSetAttribute(fused_kernel,
                         cudaFuncAttributeMaxDynamicSharedMemorySize, SMEMT);

    prep_w_kernel<<<32, 256>>>(dw);
    fused_kernel<<<BB, 512, SMEMT>>>(x, eta, phi, ck, cb, db, gm, bt, out);
}

// round 6
// speedup vs baseline: 1.0726x; 1.0726x over previous
#include <cuda_runtime.h>
#include <cuda_bf16.h>
#include <cstdint>

#define BB 256
#define NN 128
#define CC 256
#define MM 64            // rows per CTA

// B = W^T hi/lo images: [8 kchunks][256 rows][32 bf16] -> 128KB each
__device__ __align__(16) unsigned char g_Bhi[131072];
__device__ __align__(16) unsigned char g_Blo[131072];

__device__ __forceinline__ uint32_t smem_u32(const void* p) {
    uint32_t a;
    asm("{ .reg .u64 t; cvta.to.shared.u64 t, %1; cvt.u32.u64 %0, t; }"
        : "=r"(a) : "l"(p));
    return a;
}

__device__ __forceinline__ void ldsm_x4(uint32_t& r0, uint32_t& r1, uint32_t& r2,
                                        uint32_t& r3, uint32_t addr) {
    asm volatile("ldmatrix.sync.aligned.m8n8.x4.shared.b16 {%0,%1,%2,%3}, [%4];"
                 : "=r"(r0), "=r"(r1), "=r"(r2), "=r"(r3) : "r"(addr));
}

__device__ __forceinline__ void mma16816(float* d, const uint32_t* a, const uint32_t* b) {
    asm volatile(
        "mma.sync.aligned.m16n8k16.row.col.f32.bf16.bf16.f32 "
        "{%0,%1,%2,%3}, {%4,%5,%6,%7}, {%8,%9}, {%0,%1,%2,%3};"
        : "+f"(d[0]), "+f"(d[1]), "+f"(d[2]), "+f"(d[3])
        : "r"(a[0]), "r"(a[1]), "r"(a[2]), "r"(a[3]), "r"(b[0]), "r"(b[1]));
}

__device__ __forceinline__ void cp16(uint32_t dst, const void* src) {
    asm volatile("cp.async.cg.shared.global [%0], [%1], 16;" :: "r"(dst), "l"(src));
}
#define CP_COMMIT() asm volatile("cp.async.commit_group;" ::: "memory")
#define CP_WAIT0()  asm volatile("cp.async.wait_group 0;" ::: "memory")
#define CP_WAIT1()  asm volatile("cp.async.wait_group 1;" ::: "memory")

__device__ __forceinline__ void split_pack(const float* a, uint32_t* hi, uint32_t* lo) {
    #pragma unroll
    for (int u = 0; u < 4; u++) {
        float a0 = a[2 * u], a1 = a[2 * u + 1];
        __nv_bfloat16 h0 = __float2bfloat16(a0);
        __nv_bfloat16 h1 = __float2bfloat16(a1);
        __nv_bfloat16 l0 = __float2bfloat16(a0 - __bfloat162float(h0));
        __nv_bfloat16 l1 = __float2bfloat16(a1 - __bfloat162float(h1));
        hi[u] = ((uint32_t)__bfloat16_as_ushort(h1) << 16) | __bfloat16_as_ushort(h0);
        lo[u] = ((uint32_t)__bfloat16_as_ushort(l1) << 16) | __bfloat16_as_ushort(l0);
    }
}

// ---------------------------------------------------------------------------
// Kernel 0: W^T hi/lo images (coalesced).
// ---------------------------------------------------------------------------
__global__ void __launch_bounds__(256) prep_w_kernel(const float* __restrict__ W) {
    int e = blockIdx.x * 256 + threadIdx.x;   // 8192
    int lane = e & 31;
    int w = e >> 5;
    int n = (w & 7) * 32 + lane;
    int k0 = (w >> 3) * 8;
    float a[8];
    #pragma unroll
    for (int u = 0; u < 8; u++) a[u] = W[(size_t)(k0 + u) * CC + n];
    uint32_t hi[4], lo[4];
    split_pack(a, hi, lo);
    size_t off = (size_t)(k0 >> 5) * 16384 + n * 64 + (k0 & 31) * 2;
    *(uint4*)(g_Bhi + off) = make_uint4(hi[0], hi[1], hi[2], hi[3]);
    *(uint4*)(g_Blo + off) = make_uint4(lo[0], lo[1], lo[2], lo[3]);
}

// ---------------------------------------------------------------------------
// Fused kernel: grid 512 (2 CTAs/batch, 64 rows each), 256 threads, 2 CTAs/SM.
// SMEM:
//  SA  [0,65536):      A bf16 hi/lo image [8 chunks 8KB][64 rows 128B], quad-XOR
//                      swizzle. Epilogue aliases redS/redQ/smi at SA+0.
//  SB0 [65536,+20480): B hi half-buffer (256 rows x 80B)
//  SB1 [86016,+20480): B lo half-buffer; holds conv shK (9KB) during prologue
//  SNB [106496,+6144): nb ushort[64][48] (4 segments of 12)
//  SMS [112640,+1536): sge[128] | sgp[128] | scnt u8[64][4] | wmin | mins
// ---------------------------------------------------------------------------
#define ROWPAD 80
#define SA    0
#define SB0   65536
#define SB1   86016
#define SNB   106496
#define SMS   112640
#define SMEMT 114176

__global__ void __launch_bounds__(256, 2) fused_kernel(
    const float* __restrict__ x, const float* __restrict__ eta,
    const float* __restrict__ phi, const float* __restrict__ ck,
    const float* __restrict__ cb, const float* __restrict__ db,
    const float* __restrict__ gamma, const float* __restrict__ beta,
    float* __restrict__ out)
{
    extern __shared__ char smem[];
    uint32_t sb = smem_u32(smem);
    int b = blockIdx.x >> 1;
    int h = blockIdx.x & 1;
    int t = threadIdx.x;
    int lane = t & 31;
    int w = t >> 5;

    const float* xb = x + (size_t)b * NN * CC;

    auto copy_half = [&](uint32_t slot, const unsigned char* g, int kc) {
        #pragma unroll
        for (int p = 0; p < 4; p++) {
            int idx = t + p * 256;            // 1024 uint4 = 16KB
            int row = idx >> 2, seg = idx & 3;
            cp16(slot + row * ROWPAD + seg * 16, g + (size_t)kc * 16384 + idx * 16);
        }
    };

    // prefetch bhi(0)
    copy_half(sb + SB0, g_Bhi, 0);
    CP_COMMIT();

    int*   sge  = (int*)(smem + SMS);
    int*   sgp  = (int*)(smem + SMS + 512);
    unsigned char* scnt = (unsigned char*)(smem + SMS + 1024);
    float* wmin = (float*)(smem + SMS + 1280);
    float* mins = (float*)(smem + SMS + 1344);
    float* shK  = (float*)(smem + SB1);                 // dead before blo0 copy
    unsigned short* nb = (unsigned short*)(smem + SNB); // [64][48]

    // ---- per-batch min (all 128 values) ----
    float ve = (t < NN) ? eta[b * NN + t] : 1e30f;
    float vp = (t < NN) ? phi[b * NN + t] : 1e30f;
    #pragma unroll
    for (int o = 16; o > 0; o >>= 1) {
        ve = fminf(ve, __shfl_xor_sync(0xffffffffu, ve, o));
        vp = fminf(vp, __shfl_xor_sync(0xffffffffu, vp, o));
    }
    if (lane == 0 && w < 4) { wmin[w] = ve; wmin[4 + w] = vp; }
    __syncthreads();
    if (t == 0) {
        mins[0] = fminf(fminf(wmin[0], wmin[1]), fminf(wmin[2], wmin[3]));
        mins[1] = fminf(fminf(wmin[4], wmin[5]), fminf(wmin[6], wmin[7]));
    }
    __syncthreads();
    if (t < NN) {
        sge[t] = (int)((eta[b * NN + t] - mins[0]) / 0.05f);
        sgp[t] = (int)((phi[b * NN + t] - mins[1]) / 0.05f);
    }
    __syncthreads();

    // ---- stage conv kernel into SB1 region ----
    for (int i = t; i < 9 * CC; i += 256) shK[i] = ck[i];

    // ---- neighbor lists: 4 threads per particle, 32 j's each, cap 12/seg ----
    {
        int il = t >> 2;                 // local particle 0..63
        int sg = t & 3;                  // segment
        int ip = h * MM + il;            // global particle
        int gi = sge[ip], pi = sgp[ip];
        int cnt = 0;
        unsigned short* seg = nb + il * 48 + sg * 12;
        int j0 = sg * 32;
        for (int j = j0; j < j0 + 32; j++) {
            unsigned dg = (unsigned)(sge[j] - gi + 1);
            unsigned dp = (unsigned)(sgp[j] - pi + 1);
            if (dg <= 2u && dp <= 2u && cnt < 12)
                seg[cnt++] = (unsigned short)(j | ((dg * 3 + dp) << 8));
        }
        scnt[il * 4 + sg] = (unsigned char)cnt;
    }
    __syncthreads();

    // ---- conv -> SMEM A (bf16 hi/lo, quad-XOR swizzle) ----
    {
        int c0 = lane * 8;
        float4 bi0 = *(const float4*)(cb + c0);
        float4 bi1 = *(const float4*)(cb + c0 + 4);
        char* achunk = smem + SA + (lane >> 2) * 8192;
        uint32_t qbh = (uint32_t)(lane & 3);
        uint32_t qbl = (uint32_t)(4 + (lane & 3));

        #pragma unroll
        for (int s = 0; s < 8; s++) {
            int il = w * 8 + s;
            float acc[8] = { bi0.x, bi0.y, bi0.z, bi0.w, bi1.x, bi1.y, bi1.z, bi1.w };

            #pragma unroll
            for (int sg = 0; sg < 4; sg++) {
                int cnt = scnt[il * 4 + sg];
                const unsigned short* seg = nb + il * 48 + sg * 12;
                for (int e = 0; e < cnt; e++) {
                    int pk = seg[e];
                    int j = pk & 0xFF;
                    int kk = pk >> 8;
                    const float4* xp = (const float4*)(xb + (size_t)j * CC + c0);
                    float4 a0 = xp[0];
                    float4 a1 = xp[1];
                    const float4* kp = (const float4*)(shK + kk * CC + c0);
                    float4 k0 = kp[0];
                    float4 k1 = kp[1];
                    acc[0] += k0.x * a0.x; acc[1] += k0.y * a0.y;
                    acc[2] += k0.z * a0.z; acc[3] += k0.w * a0.w;
                    acc[4] += k1.x * a1.x; acc[5] += k1.y * a1.y;
                    acc[6] += k1.z * a1.z; acc[7] += k1.w * a1.w;
                }
            }

            uint32_t hi[4], lo[4];
            split_pack(acc, hi, lo);
            char* ap = achunk + il * 128;
            uint32_t r7 = (uint32_t)(il & 7);
            *(uint4*)(ap + ((qbh ^ r7) * 16)) = make_uint4(hi[0], hi[1], hi[2], hi[3]);
            *(uint4*)(ap + ((qbl ^ r7) * 16)) = make_uint4(lo[0], lo[1], lo[2], lo[3]);
        }
    }
    __syncthreads();          // A complete; shK dead

    // blo(0) -> SB1
    copy_half(sb + SB1, g_Blo, 0);
    CP_COMMIT();
    CP_WAIT1();               // bhi(0) ready
    __syncthreads();

    // ---- GEMM: M=64 N=256 K=256, 8 warps, warp tile 32x64 ----
    int mw = w & 1;           // 32-row half
    int nw = w >> 1;          // 64-col slice (0..3)

    float acc[2][8][4];
    #pragma unroll
    for (int i = 0; i < 2; i++)
        #pragma unroll
        for (int j = 0; j < 8; j++)
            #pragma unroll
            for (int d = 0; d < 4; d++) acc[i][j][d] = 0.f;

    int aRow = (lane & 7) + ((lane >> 3) & 1) * 8;
    uint32_t l7 = (uint32_t)(lane & 7);
    uint32_t qk = (uint32_t)(lane >> 4);
    uint32_t qhi[2], qlo[2];
    #pragma unroll
    for (int ks = 0; ks < 2; ks++) {
        qhi[ks] = (((uint32_t)(ks * 2) + qk) ^ l7) * 16;
        qlo[ks] = (((uint32_t)(4 + ks * 2) + qk) ^ l7) * 16;
    }
    uint32_t aBase = sb + SA + (mw * 32 + aRow) * 128;

    int bRow = (lane & 7) + ((lane >= 16) ? 8 : 0);
    uint32_t bKb = (uint32_t)(((lane >> 3) & 1) * 16);
    uint32_t bOff = (uint32_t)((nw * 64 + bRow) * ROWPAD) + bKb;

    for (int kc = 0; kc < 8; kc++) {
        uint32_t ca = aBase + kc * 8192;
        // --- hi phase: (Ahi + Alo) @ Bhi, reads SB0 ---
        #pragma unroll
        for (int ks = 0; ks < 2; ks++) {
            uint32_t ahi[2][4], alo[2][4], bf[8][2];
            #pragma unroll
            for (int mt = 0; mt < 2; mt++) {
                uint32_t a = ca + mt * 2048;
                ldsm_x4(ahi[mt][0], ahi[mt][1], ahi[mt][2], ahi[mt][3], a + qhi[ks]);
                ldsm_x4(alo[mt][0], alo[mt][1], alo[mt][2], alo[mt][3], a + qlo[ks]);
            }
            #pragma unroll
            for (int np = 0; np < 4; np++) {
                uint32_t r0, r1, r2, r3;
                ldsm_x4(r0, r1, r2, r3, sb + SB0 + bOff + np * (16 * ROWPAD) + ks * 32);
                bf[2 * np][0] = r0; bf[2 * np][1] = r1;
                bf[2 * np + 1][0] = r2; bf[2 * np + 1][1] = r3;
            }
            #pragma unroll
            for (int mt = 0; mt < 2; mt++)
                #pragma unroll
                for (int nt = 0; nt < 8; nt++) {
                    mma16816(acc[mt][nt], ahi[mt], bf[nt]);
                    mma16816(acc[mt][nt], alo[mt], bf[nt]);
                }
        }
        __syncthreads();                       // done reading SB0
        if (kc < 7) { copy_half(sb + SB0, g_Bhi, kc + 1); CP_COMMIT(); }
        if (kc < 7) CP_WAIT1(); else CP_WAIT0();   // blo(kc) arrived
        __syncthreads();

        // --- lo phase: Ahi @ Blo, reads SB1 ---
        #pragma unroll
        for (int ks = 0; ks < 2; ks++) {
            uint32_t ahi[2][4], bf[8][2];
            #pragma unroll
            for (int mt = 0; mt < 2; mt++) {
                uint32_t a = ca + mt * 2048;
                ldsm_x4(ahi[mt][0], ahi[mt][1], ahi[mt][2], ahi[mt][3], a + qhi[ks]);
            }
            #pragma unroll
            for (int np = 0; np < 4; np++) {
                uint32_t r0, r1, r2, r3;
                ldsm_x4(r0, r1, r2, r3, sb + SB1 + bOff + np * (16 * ROWPAD) + ks * 32);
                bf[2 * np][0] = r0; bf[2 * np][1] = r1;
                bf[2 * np + 1][0] = r2; bf[2 * np + 1][1] = r3;
            }
            #pragma unroll
            for (int mt = 0; mt < 2; mt++)
                #pragma unroll
                for (int nt = 0; nt < 8; nt++)
                    mma16816(acc[mt][nt], ahi[mt], bf[nt]);
        }
        __syncthreads();                       // done reading SB1 (and A if kc==7)
        if (kc < 7) {
            copy_half(sb + SB1, g_Blo, kc + 1); CP_COMMIT();
            CP_WAIT1();                        // bhi(kc+1) arrived
            __syncthreads();
        }
    }

    // ---- epilogue: bias + LN + residual (reductions alias A region) ----
    float* redS = (float*)(smem + SA);          // [64][4]
    float* redQ = (float*)(smem + SA + 1024);
    float2* smi = (float2*)(smem + SA + 2048);

    int qr = lane >> 2, qc = lane & 3;
    int NW = nw * 64, MW = mw * 32;

    // per-thread column params from global (L2-hot)
    float2 dbv[8], gv[8], btv[8];
    #pragma unroll
    for (int nt = 0; nt < 8; nt++) {
        int col = NW + nt * 8 + qc * 2;
        dbv[nt] = *(const float2*)(db + col);
        gv[nt]  = *(const float2*)(gamma + col);
        btv[nt] = *(const float2*)(beta + col);
    }

    float S[2][2], Q[2][2];
    #pragma unroll
    for (int mt = 0; mt < 2; mt++) { S[mt][0] = S[mt][1] = 0.f; Q[mt][0] = Q[mt][1] = 0.f; }
    #pragma unroll
    for (int mt = 0; mt < 2; mt++)
        #pragma unroll
        for (int nt = 0; nt < 8; nt++)
            #pragma unroll
            for (int d = 0; d < 4; d++) {
                float v = acc[mt][nt][d] + ((d & 1) ? dbv[nt].y : dbv[nt].x);
                acc[mt][nt][d] = v;
                S[mt][d >> 1] += v;
                Q[mt][d >> 1] += v * v;
            }
    #pragma unroll
    for (int mt = 0; mt < 2; mt++)
        #pragma unroll
        for (int hh = 0; hh < 2; hh++) {
            #pragma unroll
            for (int off = 1; off <= 2; off <<= 1) {
                S[mt][hh] += __shfl_xor_sync(0xffffffffu, S[mt][hh], off);
                Q[mt][hh] += __shfl_xor_sync(0xffffffffu, Q[mt][hh], off);
            }
        }
    if (qc == 0) {
        #pragma unroll
        for (int mt = 0; mt < 2; mt++)
            #pragma unroll
            for (int hh = 0; hh < 2; hh++) {
                int row = MW + mt * 16 + qr + hh * 8;
                redS[row * 4 + nw] = S[mt][hh];
                redQ[row * 4 + nw] = Q[mt][hh];
            }
    }
    __syncthreads();

    if (t < MM) {
        float s = redS[t * 4] + redS[t * 4 + 1] + redS[t * 4 + 2] + redS[t * 4 + 3];
        float q = redQ[t * 4] + redQ[t * 4 + 1] + redQ[t * 4 + 2] + redQ[t * 4 + 3];
        float mean = s * (1.0f / 256.0f);
        float var = fmaf(-mean, mean, q * (1.0f / 256.0f));
        smi[t] = make_float2(mean, rsqrtf(var + 1e-6f));
    }
    __syncthreads();

    #pragma unroll
    for (int mt = 0; mt < 2; mt++)
        #pragma unroll
        for (int hh = 0; hh < 2; hh++) {
            int row = MW + mt * 16 + qr + hh * 8;
            float2 mv = smi[row];
            size_t rb = ((size_t)b * NN + h * MM + row) * CC;
            #pragma unroll
            for (int nt = 0; nt < 8; nt++) {
                int col = NW + nt * 8 + qc * 2;
                float2 xv = *(const float2*)(x + rb + col);
                float v0 = (acc[mt][nt][hh * 2]     - mv.x) * mv.y * gv[nt].x + btv[nt].x + xv.x;
                float v1 = (acc[mt][nt][hh * 2 + 1] - mv.x) * mv.y * gv[nt].y + btv[nt].y + xv.y;
                *(float2*)(out + rb + col) = make_float2(v0, v1);
            }
        }
}

extern "C" void kernel_launch(void* const* d_in, const int* in_sizes, int n_in,
                              void* d_out, int out_size) {
    const float* x   = (const float*)d_in[0];
    const float* eta = (const float*)d_in[1];
    const float* phi = (const float*)d_in[2];
    const float* ck  = (const float*)d_in[3];
    const float* cb  = (const float*)d_in[4];
    const float* dw  = (const float*)d_in[5];
    const float* db  = (const float*)d_in[6];
    const float* gm  = (const float*)d_in[7];
    const float* bt  = (const float*)d_in[8];
    float* out = (float*)d_out;

    cudaFuncSetAttribute(fused_kernel,
                         cudaFuncAttributeMaxDynamicSharedMemorySize, SMEMT);

    prep_w_kernel<<<32, 256>>>(dw);
    fused_kernel<<<2 * BB, 256, SMEMT>>>(x, eta, phi, ck, cb, db, gm, bt, out);
}

// round 7
// speedup vs baseline: 1.3461x; 1.2550x over previous
#include <cuda_runtime.h>
#include <cuda_fp16.h>
#include <cstdint>

#define BB 256
#define NN 128
#define CC 256

// B = W^T fp16 image: [8 kchunks][256 rows][32 fp16] -> 128KB
__device__ __align__(16) unsigned char g_Bh[131072];

__device__ __forceinline__ uint32_t smem_u32(const void* p) {
    uint32_t a;
    asm("{ .reg .u64 t; cvta.to.shared.u64 t, %1; cvt.u32.u64 %0, t; }"
        : "=r"(a) : "l"(p));
    return a;
}

__device__ __forceinline__ void ldsm_x4(uint32_t& r0, uint32_t& r1, uint32_t& r2,
                                        uint32_t& r3, uint32_t addr) {
    asm volatile("ldmatrix.sync.aligned.m8n8.x4.shared.b16 {%0,%1,%2,%3}, [%4];"
                 : "=r"(r0), "=r"(r1), "=r"(r2), "=r"(r3) : "r"(addr));
}

__device__ __forceinline__ void mma16816(float* d, const uint32_t* a, const uint32_t* b) {
    asm volatile(
        "mma.sync.aligned.m16n8k16.row.col.f32.f16.f16.f32 "
        "{%0,%1,%2,%3}, {%4,%5,%6,%7}, {%8,%9}, {%0,%1,%2,%3};"
        : "+f"(d[0]), "+f"(d[1]), "+f"(d[2]), "+f"(d[3])
        : "r"(a[0]), "r"(a[1]), "r"(a[2]), "r"(a[3]), "r"(b[0]), "r"(b[1]));
}

__device__ __forceinline__ void cp16(uint32_t dst, const void* src) {
    asm volatile("cp.async.cg.shared.global [%0], [%1], 16;" :: "r"(dst), "l"(src));
}

// fp16 split: hi = f16(a), lo = f16(a - hi)
__device__ __forceinline__ void split_pack_f16(const float* a, uint32_t* hi, uint32_t* lo) {
    #pragma unroll
    for (int u = 0; u < 4; u++) {
        float a0 = a[2 * u], a1 = a[2 * u + 1];
        __half h0 = __float2half_rn(a0);
        __half h1 = __float2half_rn(a1);
        __half l0 = __float2half_rn(a0 - __half2float(h0));
        __half l1 = __float2half_rn(a1 - __half2float(h1));
        hi[u] = ((uint32_t)__half_as_ushort(h1) << 16) | __half_as_ushort(h0);
        lo[u] = ((uint32_t)__half_as_ushort(l1) << 16) | __half_as_ushort(l0);
    }
}

// ---------------------------------------------------------------------------
// Kernel 0: W^T fp16 image (coalesced).
// ---------------------------------------------------------------------------
__global__ void __launch_bounds__(256) prep_w_kernel(const float* __restrict__ W) {
    int e = blockIdx.x * 256 + threadIdx.x;   // 8192
    int lane = e & 31;
    int w = e >> 5;
    int n = (w & 7) * 32 + lane;
    int k0 = (w >> 3) * 8;
    uint32_t hv[4];
    #pragma unroll
    for (int u = 0; u < 4; u++) {
        float a0 = W[(size_t)(k0 + 2 * u) * CC + n];
        float a1 = W[(size_t)(k0 + 2 * u + 1) * CC + n];
        __half h0 = __float2half_rn(a0);
        __half h1 = __float2half_rn(a1);
        hv[u] = ((uint32_t)__half_as_ushort(h1) << 16) | __half_as_ushort(h0);
    }
    size_t off = (size_t)(k0 >> 5) * 16384 + n * 64 + (k0 & 31) * 2;
    *(uint4*)(g_Bh + off) = make_uint4(hv[0], hv[1], hv[2], hv[3]);
}

// ---------------------------------------------------------------------------
// Fused kernel: conv -> SMEM A (fp16 hi/lo, quad-XOR swizzle) -> 2-term HMMA
// GEMM + bias + LN + residual. 1 CTA/batch, 512 threads (16 warps, 64x32 tile).
// ---------------------------------------------------------------------------
#define ROWPAD 80
#define SA      0               // 131072 : A image [8 chunks 16KB][128 rows 128B]
#define SB      131072          // 2 stages x 20480 (B fp16, rows padded 80B)
#define STAGE   20480
#define SNB     172032          // nb ushort[128][128] = 32768
#define SPAR    204800          // db, gamma, beta (3 x 1024)
#define SRED    207872          // redS 4096 + redQ 4096 (shK 9216 aliases SRED+SMI)
#define SMI     216064          // float2[128]
#define SMISC   217088          // shB 1024 | sge 512 | sgp 512 | scnt 512 | wmin 64 | mins 8
#define SMEMT   219776

__global__ void __launch_bounds__(512, 1) fused_kernel(
    const float* __restrict__ x, const float* __restrict__ eta,
    const float* __restrict__ phi, const float* __restrict__ ck,
    const float* __restrict__ cb, const float* __restrict__ db,
    const float* __restrict__ gamma, const float* __restrict__ beta,
    float* __restrict__ out)
{
    extern __shared__ char smem[];
    uint32_t sb = smem_u32(smem);
    int b = blockIdx.x;
    int t = threadIdx.x;
    int lane = t & 31;
    int w = t >> 5;

    const float* xb = x + (size_t)b * NN * CC;

    auto copy_stage = [&](int s, int kc) {
        uint32_t st = sb + SB + s * STAGE;
        #pragma unroll
        for (int p = 0; p < 2; p++) {
            int idx = t + p * 512;            // 1024 uint4 = 16KB
            int row = idx >> 2, seg = idx & 3;
            cp16(st + row * ROWPAD + seg * 16, g_Bh + (size_t)kc * 16384 + idx * 16);
        }
    };

    // ---- B chunk 0 prefetch (overlaps conv phase) ----
    copy_stage(0, 0);
    asm volatile("cp.async.commit_group;" ::: "memory");

    // params
    if (t < 256) {
        ((float*)(smem + SPAR))[t]        = db[t];
        ((float*)(smem + SPAR + 1024))[t] = gamma[t];
        ((float*)(smem + SPAR + 2048))[t] = beta[t];
    }

    // ---- conv-phase shared views ----
    float* shB   = (float*)(smem + SMISC);
    int*   sge   = (int*)(smem + SMISC + 1024);
    int*   sgp   = (int*)(smem + SMISC + 1536);
    int*   scnt  = (int*)(smem + SMISC + 2048);
    float* wmin  = (float*)(smem + SMISC + 2560);
    float* mins  = (float*)(smem + SMISC + 2624);
    float* shK   = (float*)(smem + SRED);          // 9216B spans SRED+SMI
    unsigned short (*nb)[NN] = (unsigned short (*)[NN])(smem + SNB);

    // ---- per-batch min ----
    float ve = (t < NN) ? eta[b * NN + t] : 1e30f;
    float vp = (t < NN) ? phi[b * NN + t] : 1e30f;
    #pragma unroll
    for (int o = 16; o > 0; o >>= 1) {
        ve = fminf(ve, __shfl_xor_sync(0xffffffffu, ve, o));
        vp = fminf(vp, __shfl_xor_sync(0xffffffffu, vp, o));
    }
    if (lane == 0 && w < 4) { wmin[w] = ve; wmin[4 + w] = vp; }
    __syncthreads();
    if (t == 0) {
        mins[0] = fminf(fminf(wmin[0], wmin[1]), fminf(wmin[2], wmin[3]));
        mins[1] = fminf(fminf(wmin[4], wmin[5]), fminf(wmin[6], wmin[7]));
    }
    __syncthreads();
    if (t < NN) {
        sge[t] = (int)((eta[b * NN + t] - mins[0]) / 0.05f);
        sgp[t] = (int)((phi[b * NN + t] - mins[1]) / 0.05f);
    }
    __syncthreads();

    // ---- neighbor lists (t<128), conv weights staged by the rest ----
    if (t < NN) {
        int gi = sge[t], pi = sgp[t];
        int cnt = 0;
        for (int j = 0; j < NN; j++) {
            unsigned dg = (unsigned)(sge[j] - gi + 1);
            unsigned dp = (unsigned)(sgp[j] - pi + 1);
            if (dg <= 2u && dp <= 2u)
                nb[t][cnt++] = (unsigned short)(j | ((dg * 3 + dp) << 8));
        }
        scnt[t] = cnt;
    } else {
        for (int i = t - 128; i < 9 * CC; i += 384) shK[i] = ck[i];
        if (t >= 256) shB[t - 256] = cb[t - 256];
    }
    __syncthreads();

    // ---- conv -> SMEM A (fp16 hi/lo, quad-XOR swizzle) ----
    {
        int c0 = lane * 8;
        char* achunk = smem + SA + (lane >> 2) * 16384;   // chunk = c0>>5
        uint32_t qbh = (uint32_t)(lane & 3);
        uint32_t qbl = (uint32_t)(4 + (lane & 3));

        #pragma unroll
        for (int s = 0; s < 8; s++) {
            int i = w * 8 + s;
            float acc[8];
            #pragma unroll
            for (int u = 0; u < 8; u++) acc[u] = shB[c0 + u];

            int cnt = scnt[i];
            for (int e = 0; e < cnt; e++) {
                int pk = nb[i][e];
                int j = pk & 0xFF;
                int kk = pk >> 8;
                const float4* xp = (const float4*)(xb + (size_t)j * CC + c0);
                float4 a0 = xp[0];
                float4 a1 = xp[1];
                const float4* kp = (const float4*)(shK + kk * CC + c0);
                float4 k0 = kp[0];
                float4 k1 = kp[1];
                acc[0] += k0.x * a0.x; acc[1] += k0.y * a0.y;
                acc[2] += k0.z * a0.z; acc[3] += k0.w * a0.w;
                acc[4] += k1.x * a1.x; acc[5] += k1.y * a1.y;
                acc[6] += k1.z * a1.z; acc[7] += k1.w * a1.w;
            }

            uint32_t hi[4], lo[4];
            split_pack_f16(acc, hi, lo);
            char* ap = achunk + i * 128;
            uint32_t r7 = (uint32_t)(i & 7);
            *(uint4*)(ap + ((qbh ^ r7) * 16)) = make_uint4(hi[0], hi[1], hi[2], hi[3]);
            *(uint4*)(ap + ((qbl ^ r7) * 16)) = make_uint4(lo[0], lo[1], lo[2], lo[3]);
        }
    }
    __syncthreads();

    // ---- GEMM: M=128 N=256 K=256, 16 warps, warp tile 64x32, 2 terms ----
    int mw = w & 1;
    int nw = w >> 1;

    float acc[4][4][4];
    #pragma unroll
    for (int i = 0; i < 4; i++)
        #pragma unroll
        for (int j = 0; j < 4; j++)
            #pragma unroll
            for (int d = 0; d < 4; d++) acc[i][j][d] = 0.f;

    int aRow = (lane & 7) + ((lane >> 3) & 1) * 8;
    uint32_t l7 = (uint32_t)(lane & 7);
    uint32_t qk = (uint32_t)(lane >> 4);
    uint32_t qhi[2], qlo[2];
    #pragma unroll
    for (int ks = 0; ks < 2; ks++) {
        qhi[ks] = (((uint32_t)(ks * 2) + qk) ^ l7) * 16;
        qlo[ks] = (((uint32_t)(4 + ks * 2) + qk) ^ l7) * 16;
    }
    uint32_t aBase = sb + SA + (mw * 64 + aRow) * 128;

    int bRow = (lane & 7) + ((lane >= 16) ? 8 : 0);
    uint32_t bKb = (uint32_t)(((lane >> 3) & 1) * 16);
    uint32_t bOff = (uint32_t)((nw * 32 + bRow) * ROWPAD) + bKb;

    for (int kc = 0; kc < 8; kc++) {
        asm volatile("cp.async.wait_group 0;" ::: "memory");
        __syncthreads();
        if (kc < 7) {
            copy_stage((kc + 1) & 1, kc + 1);
            asm volatile("cp.async.commit_group;" ::: "memory");
        }

        uint32_t ca = aBase + kc * 16384;
        uint32_t sB = sb + SB + (kc & 1) * STAGE + bOff;

        #pragma unroll
        for (int ks = 0; ks < 2; ks++) {
            uint32_t ahi[4][4], alo[4][4], bf[4][2];
            #pragma unroll
            for (int mt = 0; mt < 4; mt++) {
                uint32_t a = ca + mt * 2048;
                ldsm_x4(ahi[mt][0], ahi[mt][1], ahi[mt][2], ahi[mt][3], a + qhi[ks]);
                ldsm_x4(alo[mt][0], alo[mt][1], alo[mt][2], alo[mt][3], a + qlo[ks]);
            }
            #pragma unroll
            for (int np = 0; np < 2; np++) {
                uint32_t r0, r1, r2, r3;
                ldsm_x4(r0, r1, r2, r3, sB + np * (16 * ROWPAD) + ks * 32);
                bf[2 * np][0] = r0; bf[2 * np][1] = r1;
                bf[2 * np + 1][0] = r2; bf[2 * np + 1][1] = r3;
            }
            #pragma unroll
            for (int mt = 0; mt < 4; mt++)
                #pragma unroll
                for (int nt = 0; nt < 4; nt++) {
                    mma16816(acc[mt][nt], ahi[mt], bf[nt]);
                    mma16816(acc[mt][nt], alo[mt], bf[nt]);
                }
        }
    }

    // ---- epilogue: bias + LN + residual ----
    const float* s_db = (const float*)(smem + SPAR);
    const float* s_g  = (const float*)(smem + SPAR + 1024);
    const float* s_bt = (const float*)(smem + SPAR + 2048);
    float* redS = (float*)(smem + SRED);
    float* redQ = (float*)(smem + SRED + 4096);
    float2* smi = (float2*)(smem + SMI);

    int qr = lane >> 2, qc = lane & 3;
    int MW = mw * 64, NW = nw * 32;

    float S[4][2], Q[4][2];
    #pragma unroll
    for (int mt = 0; mt < 4; mt++) {
        S[mt][0] = S[mt][1] = 0.f;
        Q[mt][0] = Q[mt][1] = 0.f;
    }
    #pragma unroll
    for (int mt = 0; mt < 4; mt++)
        #pragma unroll
        for (int nt = 0; nt < 4; nt++)
            #pragma unroll
            for (int d = 0; d < 4; d++) {
                int col = NW + nt * 8 + qc * 2 + (d & 1);
                float v = acc[mt][nt][d] + s_db[col];
                acc[mt][nt][d] = v;
                S[mt][d >> 1] += v;
                Q[mt][d >> 1] += v * v;
            }
    #pragma unroll
    for (int mt = 0; mt < 4; mt++)
        #pragma unroll
        for (int h = 0; h < 2; h++) {
            #pragma unroll
            for (int off = 1; off <= 2; off <<= 1) {
                S[mt][h] += __shfl_xor_sync(0xffffffffu, S[mt][h], off);
                Q[mt][h] += __shfl_xor_sync(0xffffffffu, Q[mt][h], off);
            }
        }
    __syncthreads();   // shK/smi region reuse safe
    if (qc == 0) {
        #pragma unroll
        for (int mt = 0; mt < 4; mt++)
            #pragma unroll
            for (int h = 0; h < 2; h++) {
                int row = MW + mt * 16 + qr + h * 8;
                redS[row * 8 + nw] = S[mt][h];
                redQ[row * 8 + nw] = Q[mt][h];
            }
    }
    __syncthreads();

    if (t < 128) {
        float s = 0.f, q = 0.f;
        #pragma unroll
        for (int k = 0; k < 8; k++) {
            s += redS[t * 8 + k];
            q += redQ[t * 8 + k];
        }
        float mean = s * (1.0f / 256.0f);
        float var = fmaf(-mean, mean, q * (1.0f / 256.0f));
        smi[t] = make_float2(mean, rsqrtf(var + 1e-6f));
    }
    __syncthreads();

    #pragma unroll
    for (int mt = 0; mt < 4; mt++)
        #pragma unroll
        for (int h = 0; h < 2; h++) {
            int row = MW + mt * 16 + qr + h * 8;
            float2 mv = smi[row];
            size_t rb = ((size_t)b * NN + row) * CC;
            #pragma unroll
            for (int nt = 0; nt < 4; nt++) {
                int col = NW + nt * 8 + qc * 2;
                float2 xv = *(const float2*)(x + rb + col);
                float v0 = (acc[mt][nt][h * 2]     - mv.x) * mv.y * s_g[col]     + s_bt[col]     + xv.x;
                float v1 = (acc[mt][nt][h * 2 + 1] - mv.x) * mv.y * s_g[col + 1] + s_bt[col + 1] + xv.y;
                *(float2*)(out + rb + col) = make_float2(v0, v1);
            }
        }
}

extern "C" void kernel_launch(void* const* d_in, const int* in_sizes, int n_in,
                              void* d_out, int out_size) {
    const float* x   = (const float*)d_in[0];
    const float* eta = (const float*)d_in[1];
    const float* phi = (const float*)d_in[2];
    const float* ck  = (const float*)d_in[3];
    const float* cb  = (const float*)d_in[4];
    const float* dw  = (const float*)d_in[5];
    const float* db  = (const float*)d_in[6];
    const float* gm  = (const float*)d_in[7];
    const float* bt  = (const float*)d_in[8];
    float* out = (float*)d_out;

    cudaFuncSetAttribute(fused_kernel,
                         cudaFuncAttributeMaxDynamicSharedMemorySize, SMEMT);

    prep_w_kernel<<<32, 256>>>(dw);
    fused_kernel<<<BB, 512, SMEMT>>>(x, eta, phi, ck, cb, db, gm, bt, out);
}

// round 8
// speedup vs baseline: 1.6654x; 1.2372x over previous
#include <cuda_runtime.h>
#include <cuda_fp16.h>
#include <cstdint>

#define BB 256
#define NN 128
#define CC 256

// B = W^T fp16 image: [8 kchunks][256 rows][32 fp16] -> 128KB
__device__ __align__(16) unsigned char g_Bh[131072];

__device__ __forceinline__ uint32_t smem_u32(const void* p) {
    uint32_t a;
    asm("{ .reg .u64 t; cvta.to.shared.u64 t, %1; cvt.u32.u64 %0, t; }"
        : "=r"(a) : "l"(p));
    return a;
}

__device__ __forceinline__ void ldsm_x4(uint32_t& r0, uint32_t& r1, uint32_t& r2,
                                        uint32_t& r3, uint32_t addr) {
    asm volatile("ldmatrix.sync.aligned.m8n8.x4.shared.b16 {%0,%1,%2,%3}, [%4];"
                 : "=r"(r0), "=r"(r1), "=r"(r2), "=r"(r3) : "r"(addr));
}

__device__ __forceinline__ void mma16816(float* d, const uint32_t* a, const uint32_t* b) {
    asm volatile(
        "mma.sync.aligned.m16n8k16.row.col.f32.f16.f16.f32 "
        "{%0,%1,%2,%3}, {%4,%5,%6,%7}, {%8,%9}, {%0,%1,%2,%3};"
        : "+f"(d[0]), "+f"(d[1]), "+f"(d[2]), "+f"(d[3])
        : "r"(a[0]), "r"(a[1]), "r"(a[2]), "r"(a[3]), "r"(b[0]), "r"(b[1]));
}

__device__ __forceinline__ void cp16(uint32_t dst, const void* src) {
    asm volatile("cp.async.cg.shared.global [%0], [%1], 16;" :: "r"(dst), "l"(src));
}

__device__ __forceinline__ void pack_f16(const float* a, uint32_t* hv) {
    #pragma unroll
    for (int u = 0; u < 4; u++) {
        __half h0 = __float2half_rn(a[2 * u]);
        __half h1 = __float2half_rn(a[2 * u + 1]);
        hv[u] = ((uint32_t)__half_as_ushort(h1) << 16) | __half_as_ushort(h0);
    }
}

// ---------------------------------------------------------------------------
// Kernel 0: W^T fp16 image (coalesced).
// ---------------------------------------------------------------------------
__global__ void __launch_bounds__(256) prep_w_kernel(const float* __restrict__ W) {
    int e = blockIdx.x * 256 + threadIdx.x;   // 8192
    int lane = e & 31;
    int w = e >> 5;
    int n = (w & 7) * 32 + lane;
    int k0 = (w >> 3) * 8;
    float a[8];
    #pragma unroll
    for (int u = 0; u < 8; u++) a[u] = W[(size_t)(k0 + u) * CC + n];
    uint32_t hv[4];
    pack_f16(a, hv);
    size_t off = (size_t)(k0 >> 5) * 16384 + n * 64 + (k0 & 31) * 2;
    *(uint4*)(g_Bh + off) = make_uint4(hv[0], hv[1], hv[2], hv[3]);
}

// ---------------------------------------------------------------------------
// Fused kernel: conv -> SMEM A (fp16, 64B rows, quad-group swizzle) -> 1-term
// fp16 HMMA GEMM + bias + LN + residual. 1 CTA/batch, 512 threads.
// A chunk layout: [128 rows][64B]; quad q stored at q ^ ((row>>1)&3).
// ---------------------------------------------------------------------------
#define ROWPAD 80
#define SA      0               // 65536 : A image [8 chunks 8KB][128 rows 64B]
#define SB      65536           // 2 stages x 20480 (B fp16, rows padded 80B)
#define STAGE   20480
#define SNB     106496          // nb ushort[128][128] = 32768
#define SPAR    139264          // db, gamma, beta (3 x 1024)
#define SRED    142336          // redS 4096 + redQ 4096 (shK 9216 aliases SRED+SMI)
#define SMI     150528          // float2[128]
#define SMISC   151552          // shB 1024 | sge 512 | sgp 512 | scnt 512 | wmin 64 | mins 8
#define SMEMT   154624

__global__ void __launch_bounds__(512, 1) fused_kernel(
    const float* __restrict__ x, const float* __restrict__ eta,
    const float* __restrict__ phi, const float* __restrict__ ck,
    const float* __restrict__ cb, const float* __restrict__ db,
    const float* __restrict__ gamma, const float* __restrict__ beta,
    float* __restrict__ out)
{
    extern __shared__ char smem[];
    uint32_t sb = smem_u32(smem);
    int b = blockIdx.x;
    int t = threadIdx.x;
    int lane = t & 31;
    int w = t >> 5;

    const float* xb = x + (size_t)b * NN * CC;

    auto copy_stage = [&](int s, int kc) {
        uint32_t st = sb + SB + s * STAGE;
        #pragma unroll
        for (int p = 0; p < 2; p++) {
            int idx = t + p * 512;            // 1024 uint4 = 16KB
            int row = idx >> 2, seg = idx & 3;
            cp16(st + row * ROWPAD + seg * 16, g_Bh + (size_t)kc * 16384 + idx * 16);
        }
    };

    // ---- B chunk 0 prefetch (overlaps conv phase) ----
    copy_stage(0, 0);
    asm volatile("cp.async.commit_group;" ::: "memory");

    // params
    if (t < 256) {
        ((float*)(smem + SPAR))[t]        = db[t];
        ((float*)(smem + SPAR + 1024))[t] = gamma[t];
        ((float*)(smem + SPAR + 2048))[t] = beta[t];
    }

    // ---- conv-phase shared views ----
    float* shB   = (float*)(smem + SMISC);
    int*   sge   = (int*)(smem + SMISC + 1024);
    int*   sgp   = (int*)(smem + SMISC + 1536);
    int*   scnt  = (int*)(smem + SMISC + 2048);
    float* wmin  = (float*)(smem + SMISC + 2560);
    float* mins  = (float*)(smem + SMISC + 2624);
    float* shK   = (float*)(smem + SRED);          // 9216B spans SRED+SMI
    unsigned short (*nb)[NN] = (unsigned short (*)[NN])(smem + SNB);

    // ---- per-batch min ----
    float ve = (t < NN) ? eta[b * NN + t] : 1e30f;
    float vp = (t < NN) ? phi[b * NN + t] : 1e30f;
    #pragma unroll
    for (int o = 16; o > 0; o >>= 1) {
        ve = fminf(ve, __shfl_xor_sync(0xffffffffu, ve, o));
        vp = fminf(vp, __shfl_xor_sync(0xffffffffu, vp, o));
    }
    if (lane == 0 && w < 4) { wmin[w] = ve; wmin[4 + w] = vp; }
    __syncthreads();
    if (t == 0) {
        mins[0] = fminf(fminf(wmin[0], wmin[1]), fminf(wmin[2], wmin[3]));
        mins[1] = fminf(fminf(wmin[4], wmin[5]), fminf(wmin[6], wmin[7]));
    }
    __syncthreads();
    if (t < NN) {
        sge[t] = (int)((eta[b * NN + t] - mins[0]) / 0.05f);
        sgp[t] = (int)((phi[b * NN + t] - mins[1]) / 0.05f);
    }
    __syncthreads();

    // ---- neighbor lists (t<128), conv weights staged by the rest ----
    if (t < NN) {
        int gi = sge[t], pi = sgp[t];
        int cnt = 0;
        for (int j = 0; j < NN; j++) {
            unsigned dg = (unsigned)(sge[j] - gi + 1);
            unsigned dp = (unsigned)(sgp[j] - pi + 1);
            if (dg <= 2u && dp <= 2u)
                nb[t][cnt++] = (unsigned short)(j | ((dg * 3 + dp) << 8));
        }
        scnt[t] = cnt;
    } else {
        for (int i = t - 128; i < 9 * CC; i += 384) shK[i] = ck[i];
        if (t >= 256) shB[t - 256] = cb[t - 256];
    }
    __syncthreads();

    // ---- conv -> SMEM A (fp16, quad-group swizzle) ----
    {
        int c0 = lane * 8;
        char* achunk = smem + SA + (lane >> 2) * 8192;    // chunk = c0>>5
        uint32_t q = (uint32_t)(lane & 3);                // quad within row

        #pragma unroll
        for (int s = 0; s < 8; s++) {
            int i = w * 8 + s;
            float acc[8];
            #pragma unroll
            for (int u = 0; u < 8; u++) acc[u] = shB[c0 + u];

            int cnt = scnt[i];
            for (int e = 0; e < cnt; e++) {
                int pk = nb[i][e];
                int j = pk & 0xFF;
                int kk = pk >> 8;
                const float4* xp = (const float4*)(xb + (size_t)j * CC + c0);
                float4 a0 = xp[0];
                float4 a1 = xp[1];
                const float4* kp = (const float4*)(shK + kk * CC + c0);
                float4 k0 = kp[0];
                float4 k1 = kp[1];
                acc[0] += k0.x * a0.x; acc[1] += k0.y * a0.y;
                acc[2] += k0.z * a0.z; acc[3] += k0.w * a0.w;
                acc[4] += k1.x * a1.x; acc[5] += k1.y * a1.y;
                acc[6] += k1.z * a1.z; acc[7] += k1.w * a1.w;
            }

            uint32_t hv[4];
            pack_f16(acc, hv);
            uint32_t qs = q ^ ((uint32_t)(i >> 1) & 3u);
            *(uint4*)(achunk + i * 64 + qs * 16) = make_uint4(hv[0], hv[1], hv[2], hv[3]);
        }
    }
    __syncthreads();

    // ---- GEMM: M=128 N=256 K=256, 16 warps, warp tile 64x32, 1 term ----
    int mw = w & 1;
    int nw = w >> 1;

    float acc[4][4][4];
    #pragma unroll
    for (int i = 0; i < 4; i++)
        #pragma unroll
        for (int j = 0; j < 4; j++)
            #pragma unroll
            for (int d = 0; d < 4; d++) acc[i][j][d] = 0.f;

    int aRow0 = mw * 64 + (lane & 7) + ((lane >> 3) & 1) * 8;   // + mt*16
    uint32_t qk = (uint32_t)(lane >> 4);                         // 16B half of 32B

    int bRow = (lane & 7) + ((lane >= 16) ? 8 : 0);
    uint32_t bKb = (uint32_t)(((lane >> 3) & 1) * 16);
    uint32_t bOff = (uint32_t)((nw * 32 + bRow) * ROWPAD) + bKb;

    for (int kc = 0; kc < 8; kc++) {
        asm volatile("cp.async.wait_group 0;" ::: "memory");
        __syncthreads();
        if (kc < 7) {
            copy_stage((kc + 1) & 1, kc + 1);
            asm volatile("cp.async.commit_group;" ::: "memory");
        }

        uint32_t ca = sb + SA + kc * 8192;
        uint32_t sB = sb + SB + (kc & 1) * STAGE + bOff;

        #pragma unroll
        for (int ks = 0; ks < 2; ks++) {
            uint32_t av[4][4], bf[4][2];
            #pragma unroll
            for (int mt = 0; mt < 4; mt++) {
                int row = aRow0 + mt * 16;
                uint32_t qs = (((uint32_t)(ks * 2) + qk) ^ ((uint32_t)(row >> 1) & 3u)) * 16;
                ldsm_x4(av[mt][0], av[mt][1], av[mt][2], av[mt][3],
                        ca + row * 64 + qs);
            }
            #pragma unroll
            for (int np = 0; np < 2; np++) {
                uint32_t r0, r1, r2, r3;
                ldsm_x4(r0, r1, r2, r3, sB + np * (16 * ROWPAD) + ks * 32);
                bf[2 * np][0] = r0; bf[2 * np][1] = r1;
                bf[2 * np + 1][0] = r2; bf[2 * np + 1][1] = r3;
            }
            #pragma unroll
            for (int mt = 0; mt < 4; mt++)
                #pragma unroll
                for (int nt = 0; nt < 4; nt++)
                    mma16816(acc[mt][nt], av[mt], bf[nt]);
        }
    }

    // ---- epilogue: bias + LN + residual ----
    const float* s_db = (const float*)(smem + SPAR);
    const float* s_g  = (const float*)(smem + SPAR + 1024);
    const float* s_bt = (const float*)(smem + SPAR + 2048);
    float* redS = (float*)(smem + SRED);
    float* redQ = (float*)(smem + SRED + 4096);
    float2* smi = (float2*)(smem + SMI);

    int qr = lane >> 2, qc = lane & 3;
    int MW = mw * 64, NW = nw * 32;

    float S[4][2], Q[4][2];
    #pragma unroll
    for (int mt = 0; mt < 4; mt++) {
        S[mt][0] = S[mt][1] = 0.f;
        Q[mt][0] = Q[mt][1] = 0.f;
    }
    #pragma unroll
    for (int mt = 0; mt < 4; mt++)
        #pragma unroll
        for (int nt = 0; nt < 4; nt++)
            #pragma unroll
            for (int d = 0; d < 4; d++) {
                int col = NW + nt * 8 + qc * 2 + (d & 1);
                float v = acc[mt][nt][d] + s_db[col];
                acc[mt][nt][d] = v;
                S[mt][d >> 1] += v;
                Q[mt][d >> 1] += v * v;
            }
    #pragma unroll
    for (int mt = 0; mt < 4; mt++)
        #pragma unroll
        for (int h = 0; h < 2; h++) {
            #pragma unroll
            for (int off = 1; off <= 2; off <<= 1) {
                S[mt][h] += __shfl_xor_sync(0xffffffffu, S[mt][h], off);
                Q[mt][h] += __shfl_xor_sync(0xffffffffu, Q[mt][h], off);
            }
        }
    __syncthreads();
    if (qc == 0) {
        #pragma unroll
        for (int mt = 0; mt < 4; mt++)
            #pragma unroll
            for (int h = 0; h < 2; h++) {
                int row = MW + mt * 16 + qr + h * 8;
                redS[row * 8 + nw] = S[mt][h];
                redQ[row * 8 + nw] = Q[mt][h];
            }
    }
    __syncthreads();

    if (t < 128) {
        float s = 0.f, q = 0.f;
        #pragma unroll
        for (int k = 0; k < 8; k++) {
            s += redS[t * 8 + k];
            q += redQ[t * 8 + k];
        }
        float mean = s * (1.0f / 256.0f);
        float var = fmaf(-mean, mean, q * (1.0f / 256.0f));
        smi[t] = make_float2(mean, rsqrtf(var + 1e-6f));
    }
    __syncthreads();

    #pragma unroll
    for (int mt = 0; mt < 4; mt++)
        #pragma unroll
        for (int h = 0; h < 2; h++) {
            int row = MW + mt * 16 + qr + h * 8;
            float2 mv = smi[row];
            size_t rb = ((size_t)b * NN + row) * CC;
            #pragma unroll
            for (int nt = 0; nt < 4; nt++) {
                int col = NW + nt * 8 + qc * 2;
                float2 xv = *(const float2*)(x + rb + col);
                float v0 = (acc[mt][nt][h * 2]     - mv.x) * mv.y * s_g[col]     + s_bt[col]     + xv.x;
                float v1 = (acc[mt][nt][h * 2 + 1] - mv.x) * mv.y * s_g[col + 1] + s_bt[col + 1] + xv.y;
                *(float2*)(out + rb + col) = make_float2(v0, v1);
            }
        }
}

extern "C" void kernel_launch(void* const* d_in, const int* in_sizes, int n_in,
                              void* d_out, int out_size) {
    const float* x   = (const float*)d_in[0];
    const float* eta = (const float*)d_in[1];
    const float* phi = (const float*)d_in[2];
    const float* ck  = (const float*)d_in[3];
    const float* cb  = (const float*)d_in[4];
    const float* dw  = (const float*)d_in[5];
    const float* db  = (const float*)d_in[6];
    const float* gm  = (const float*)d_in[7];
    const float* bt  = (const float*)d_in[8];
    float* out = (float*)d_out;

    cudaFuncSetAttribute(fused_kernel,
                         cudaFuncAttributeMaxDynamicSharedMemorySize, SMEMT);

    prep_w_kernel<<<32, 256>>>(dw);
    fused_kernel<<<BB, 512, SMEMT>>>(x, eta, phi, ck, cb, db, gm, bt, out);
}